// round 6
// baseline (speedup 1.0000x reference)
#include <cuda_runtime.h>
#include <cuda_fp16.h>

#define NN 100000
#define EE 1600000
#define NB 98  // (NN + 1023) / 1024

// ---------------- scratch (static device globals; no allocation) ----------------
__device__ int    g_is64;
__device__ int    g_src[EE];
__device__ int    g_dstE[EE];
__device__ int    g_deg[NN];
__device__ int    g_rowptr[NN + 1];
__device__ int    g_cursor[NN];
__device__ int    g_bsum[128];
__device__ int    g_col[EE + NN];
__device__ __half g_h16[NN * 64];
__device__ float  g_act[NN * 64];
__device__ float  g_adst[NN * 8];
__device__ float  g_asrc[NN * 8];

// ---------------- init: deg=1 (self-loop) + dtype detect ----------------
__global__ void k_init(const void* ei) {
    int i = blockIdx.x * blockDim.x + threadIdx.x;
    if (i < NN) g_deg[i] = 1;
    if (i == 0) {
        const long long* p = (const long long*)ei;
        int ok = 1;
        for (int k = 0; k < 8; k++) {
            long long v = p[k];
            if (v < 0 || v >= NN) ok = 0;
        }
        g_is64 = ok;
    }
}

// ---------------- convert + histogram fused ----------------
__global__ void k_convhist(const void* ei) {
    int e = blockIdx.x * blockDim.x + threadIdx.x;
    if (e >= EE) return;
    int s, d;
    if (g_is64) {
        const long long* p = (const long long*)ei;
        s = (int)p[e];
        d = (int)p[EE + e];
    } else {
        const int* p = (const int*)ei;
        s = p[e];
        d = p[EE + e];
    }
    g_src[e] = s;
    g_dstE[e] = d;
    if (s != d) atomicAdd(&g_deg[d], 1);  // original self-loops dropped (exp(-1e9-amax)==0)
}

// ---------------- scan ----------------
__global__ void k_scan1() {
    __shared__ int sh[1024];
    int tid = threadIdx.x;
    int i = blockIdx.x * 1024 + tid;
    int v = (i < NN) ? g_deg[i] : 0;
    sh[tid] = v;
    __syncthreads();
    for (int o = 1; o < 1024; o <<= 1) {
        int t = (tid >= o) ? sh[tid - o] : 0;
        __syncthreads();
        sh[tid] += t;
        __syncthreads();
    }
    if (i < NN) g_rowptr[i] = sh[tid] - v;
    if (tid == 1023) g_bsum[blockIdx.x] = sh[1023];
}

__global__ void k_scan23() {
    __shared__ int sh[128];
    int tid = threadIdx.x;
    int i = blockIdx.x * 256 + tid;
    if (tid < 128) sh[tid] = (tid < NB) ? g_bsum[tid] : 0;
    __syncthreads();
    for (int o = 1; o < 128; o <<= 1) {
        int t = (tid >= o && tid < 128) ? sh[tid - o] : 0;
        __syncthreads();
        if (tid < 128) sh[tid] += t;
        __syncthreads();
    }
    if (i < NN) {
        int blk = i >> 10;
        int exc = blk ? sh[blk - 1] : 0;
        int r = g_rowptr[i] + exc;
        g_rowptr[i] = r;
        g_cursor[i] = r;
    }
    if (blockIdx.x == 0 && tid == 0) g_rowptr[NN] = sh[127];
}

__global__ void k_scatter() {
    int e = blockIdx.x * blockDim.x + threadIdx.x;
    if (e >= EE + NN) return;
    if (e < EE) {
        int s = g_src[e], d = g_dstE[e];
        if (s != d) {
            int p = atomicAdd(&g_cursor[d], 1);
            g_col[p] = s;
        }
    } else {
        int n = e - EE;
        int p = atomicAdd(&g_cursor[n], 1);
        g_col[p] = n;
    }
}

// ---------------- tiled FFMA GEMM + fused attention-dot epilogue ----------------
template <int K, int NOUT, int MROWS, int TX, int HEADS>
__global__ __launch_bounds__(256) void k_gemm(const float* __restrict__ A,
                                              const float* __restrict__ W,
                                              const float* __restrict__ att,
                                              int use_g_act) {
    __shared__ float Ws[K * NOUT];
    __shared__ float As[MROWS][36];
    const float* Ap = use_g_act ? (const float*)g_act : A;

    int tid = threadIdx.x;
    int row0 = blockIdx.x * MROWS;

    for (int i = tid; i < K * NOUT / 4; i += 256)
        ((float4*)Ws)[i] = ((const float4*)W)[i];

    int tx = tid % TX, ty = tid / TX;
    int r0 = ty * 4, c0 = tx * 4;
    float acc[4][4];
#pragma unroll
    for (int i = 0; i < 4; i++)
#pragma unroll
        for (int j = 0; j < 4; j++) acc[i][j] = 0.f;

    for (int kb = 0; kb < K; kb += 32) {
        __syncthreads();
        for (int f = tid; f < MROWS * 8; f += 256) {
            int r = f >> 3, c4 = f & 7;
            float4 v = make_float4(0.f, 0.f, 0.f, 0.f);
            if (row0 + r < NN)
                v = *(const float4*)&Ap[(row0 + r) * K + kb + c4 * 4];
            *(float4*)&As[r][c4 * 4] = v;
        }
        __syncthreads();
#pragma unroll
        for (int kk = 0; kk < 32; kk++) {
            float a0 = As[r0 + 0][kk];
            float a1 = As[r0 + 1][kk];
            float a2 = As[r0 + 2][kk];
            float a3 = As[r0 + 3][kk];
            float4 b = *(float4*)&Ws[(kb + kk) * NOUT + c0];
            acc[0][0] += a0 * b.x; acc[0][1] += a0 * b.y; acc[0][2] += a0 * b.z; acc[0][3] += a0 * b.w;
            acc[1][0] += a1 * b.x; acc[1][1] += a1 * b.y; acc[1][2] += a1 * b.z; acc[1][3] += a1 * b.w;
            acc[2][0] += a2 * b.x; acc[2][1] += a2 * b.y; acc[2][2] += a2 * b.z; acc[2][3] += a2 * b.w;
            acc[3][0] += a3 * b.x; acc[3][1] += a3 * b.y; acc[3][2] += a3 * b.z; acc[3][3] += a3 * b.w;
        }
    }
    // store h as fp16
#pragma unroll
    for (int i = 0; i < 4; i++) {
        int r = row0 + r0 + i;
        if (r < NN) {
            __half2 lo = __floats2half2_rn(acc[i][0], acc[i][1]);
            __half2 hi = __floats2half2_rn(acc[i][2], acc[i][3]);
            __half2* dst = (__half2*)&g_h16[r * NOUT + c0];
            dst[0] = lo;
            dst[1] = hi;
        }
    }

    // ---- fused attention dots ----
    constexpr int CPH = NOUT / HEADS;
    constexpr int TPH = CPH / 4;
    float wd[4], wsrc[4];
#pragma unroll
    for (int j = 0; j < 4; j++) {
        int col = c0 + j;
        int h = col / CPH, c = col % CPH;
        wd[j]   = att[h * (2 * CPH) + c];
        wsrc[j] = att[h * (2 * CPH) + CPH + c];
    }
    __syncthreads();  // smem tiles dead; reuse As (dst partials) + Ws (src partials)
#pragma unroll
    for (int i = 0; i < 4; i++) {
        float pd = acc[i][0] * wd[0] + acc[i][1] * wd[1] + acc[i][2] * wd[2] + acc[i][3] * wd[3];
        float ps = acc[i][0] * wsrc[0] + acc[i][1] * wsrc[1] + acc[i][2] * wsrc[2] + acc[i][3] * wsrc[3];
        As[r0 + i][tx] = pd;
        Ws[(r0 + i) * TX + tx] = ps;
    }
    __syncthreads();
    for (int idx = tid; idx < MROWS * HEADS; idx += 256) {
        int r = idx / HEADS, h = idx % HEADS;
        float sd = 0.f, ss = 0.f;
#pragma unroll
        for (int q = 0; q < TPH; q++) {
            sd += As[r][h * TPH + q];
            ss += Ws[r * TX + h * TPH + q];
        }
        int row = row0 + r;
        if (row < NN) {
            g_adst[row * HEADS + h] = sd;
            g_asrc[row * HEADS + h] = ss;
        }
    }
}

__device__ __forceinline__ float leaky_exp(float a) {
    a = a > 0.f ? a : 0.2f * a;
    return __expf(a);
}

// ---------------- aggregate H=8: warp per node, batched straight-line ----------------
// lane covers cols 2*lane..2*lane+1, head = lane>>2. Per-lane weight recompute is
// free (one MUFU warp-instruction); no smem/sync/shfl in the loop; 4-edge batches
// give ~8 concurrent loads per warp.
__global__ __launch_bounds__(256) void k_agg8(const float* __restrict__ bias, int do_elu) {
    int t = blockIdx.x * blockDim.x + threadIdx.x;
    int n = t >> 5, lane = t & 31;
    if (n >= NN) return;
    int start = g_rowptr[n], end = g_rowptr[n + 1];
    int h = lane >> 2;

    float adst_h = g_adst[n * 8 + h];
    float2 acc = make_float2(0.f, 0.f);
    float dsum = 0.f;

    int e = start;
    for (; e + 4 <= end; e += 4) {
        int s0 = g_col[e], s1 = g_col[e + 1], s2 = g_col[e + 2], s3 = g_col[e + 3];
        float a0 = g_asrc[s0 * 8 + h];
        float a1 = g_asrc[s1 * 8 + h];
        float a2 = g_asrc[s2 * 8 + h];
        float a3 = g_asrc[s3 * 8 + h];
        float2 v0 = __half22float2(*(const __half2*)&g_h16[s0 * 64 + lane * 2]);
        float2 v1 = __half22float2(*(const __half2*)&g_h16[s1 * 64 + lane * 2]);
        float2 v2 = __half22float2(*(const __half2*)&g_h16[s2 * 64 + lane * 2]);
        float2 v3 = __half22float2(*(const __half2*)&g_h16[s3 * 64 + lane * 2]);
        float w0 = leaky_exp(adst_h + a0);
        float w1 = leaky_exp(adst_h + a1);
        float w2 = leaky_exp(adst_h + a2);
        float w3 = leaky_exp(adst_h + a3);
        acc.x += v0.x * w0 + v1.x * w1 + v2.x * w2 + v3.x * w3;
        acc.y += v0.y * w0 + v1.y * w1 + v2.y * w2 + v3.y * w3;
        dsum += (w0 + w1) + (w2 + w3);
    }
    for (; e < end; e++) {
        int s = g_col[e];
        float w = leaky_exp(adst_h + g_asrc[s * 8 + h]);
        float2 v = __half22float2(*(const __half2*)&g_h16[s * 64 + lane * 2]);
        acc.x += v.x * w;
        acc.y += v.y * w;
        dsum += w;
    }
    float inv = 1.f / dsum;
    float o0 = acc.x * inv + bias[lane * 2];
    float o1 = acc.y * inv + bias[lane * 2 + 1];
    if (do_elu) {
        o0 = o0 > 0.f ? o0 : expm1f(o0);
        o1 = o1 > 0.f ? o1 : expm1f(o1);
    }
    *(float2*)&g_act[n * 64 + lane * 2] = make_float2(o0, o1);
}

// ---------------- aggregate H=1: warp per node, half-warp per edge, batched ----------------
__global__ __launch_bounds__(256) void k_agg32(const float* __restrict__ bias,
                                               float* __restrict__ outp) {
    int t = blockIdx.x * blockDim.x + threadIdx.x;
    int n = t >> 5, lane = t & 31;
    if (n >= NN) return;
    const unsigned full = 0xffffffffu;
    int start = g_rowptr[n], end = g_rowptr[n + 1];
    int half = lane >> 4;
    int c2 = (lane & 15) * 2;

    float adst = g_adst[n];
    float2 acc = make_float2(0.f, 0.f);
    float dsum = 0.f;

    int e = start;
    for (; e + 4 <= end; e += 4) {
        int sA = g_col[e + half];
        int sB = g_col[e + 2 + half];
        float aA = g_asrc[sA];
        float aB = g_asrc[sB];
        float2 vA = __half22float2(*(const __half2*)&g_h16[sA * 32 + c2]);
        float2 vB = __half22float2(*(const __half2*)&g_h16[sB * 32 + c2]);
        float wA = leaky_exp(adst + aA);
        float wB = leaky_exp(adst + aB);
        acc.x += vA.x * wA + vB.x * wB;
        acc.y += vA.y * wA + vB.y * wB;
        dsum += wA + wB;
    }
    for (; e + 2 <= end; e += 2) {
        int s = g_col[e + half];
        float w = leaky_exp(adst + g_asrc[s]);
        float2 v = __half22float2(*(const __half2*)&g_h16[s * 32 + c2]);
        acc.x += v.x * w;
        acc.y += v.y * w;
        dsum += w;
    }
    if (e < end && half == 0) {
        int s = g_col[e];
        float w = leaky_exp(adst + g_asrc[s]);
        float2 v = __half22float2(*(const __half2*)&g_h16[s * 32 + c2]);
        acc.x += v.x * w;
        acc.y += v.y * w;
        dsum += w;
    }
    acc.x += __shfl_xor_sync(full, acc.x, 16);
    acc.y += __shfl_xor_sync(full, acc.y, 16);
    dsum += __shfl_xor_sync(full, dsum, 16);
    if (lane < 16) {
        float inv = 1.f / dsum;
        outp[n * 32 + c2] = acc.x * inv + bias[c2];
        outp[n * 32 + c2 + 1] = acc.y * inv + bias[c2 + 1];
    }
}

// ---------------- launch ----------------
extern "C" void kernel_launch(void* const* d_in, const int* in_sizes, int n_in,
                              void* d_out, int out_size) {
    const float* x    = (const float*)d_in[0];
    const void*  ei   = d_in[1];
    const float* W1   = (const float*)d_in[2];
    const float* att1 = (const float*)d_in[3];
    const float* b1   = (const float*)d_in[4];
    const float* W2   = (const float*)d_in[5];
    const float* att2 = (const float*)d_in[6];
    const float* b2   = (const float*)d_in[7];
    const float* W3   = (const float*)d_in[8];
    const float* att3 = (const float*)d_in[9];
    const float* b3   = (const float*)d_in[10];
    float* out = (float*)d_out;

    const int TB = 256;
    const int warpGrid = (NN * 32 + TB - 1) / TB;

    // CSR build (dst layer-invariant)
    k_init<<<(NN + TB - 1) / TB, TB>>>(ei);
    k_convhist<<<(EE + TB - 1) / TB, TB>>>(ei);
    k_scan1<<<NB, 1024>>>();
    k_scan23<<<(NN + 255) / 256, 256>>>();
    k_scatter<<<(EE + NN + TB - 1) / TB, TB>>>();

    // Layer 1: 128 -> 8x8
    k_gemm<128, 64, 64, 16, 8><<<(NN + 63) / 64, TB>>>(x, W1, att1, 0);
    k_agg8<<<warpGrid, TB>>>(b1, 1);

    // Layer 2: 64 -> 8x8
    k_gemm<64, 64, 64, 16, 8><<<(NN + 63) / 64, TB>>>(nullptr, W2, att2, 1);
    k_agg8<<<warpGrid, TB>>>(b2, 1);

    // Layer 3: 64 -> 1x32
    k_gemm<64, 32, 128, 8, 1><<<(NN + 127) / 128, TB>>>(nullptr, W3, att3, 1);
    k_att_dummy:;
    k_agg32<<<warpGrid, TB>>>(b3, out);
}

// round 7
// speedup vs baseline: 1.5616x; 1.5616x over previous
#include <cuda_runtime.h>
#include <cuda_fp16.h>

#define NN 100000
#define EE 1600000
#define NB 98  // (NN + 1023) / 1024

// ---------------- scratch (static device globals; no allocation) ----------------
__device__ int    g_is64;
__device__ int    g_src[EE];
__device__ int    g_dstE[EE];
__device__ int    g_deg[NN];
__device__ int    g_rowptr[NN + 1];
__device__ int    g_cursor[NN];
__device__ int    g_bsum[128];
__device__ int    g_col[EE + NN];
__device__ __half g_h16[NN * 64];
__device__ float  g_act[NN * 64];
__device__ float  g_adst[NN * 8];
__device__ float  g_asrc[NN * 8];

// ---------------- init: deg=1 (self-loop) + dtype detect ----------------
__global__ void k_init(const void* ei) {
    int i = blockIdx.x * blockDim.x + threadIdx.x;
    if (i < NN) g_deg[i] = 1;
    if (i == 0) {
        const long long* p = (const long long*)ei;
        int ok = 1;
        for (int k = 0; k < 8; k++) {
            long long v = p[k];
            if (v < 0 || v >= NN) ok = 0;
        }
        g_is64 = ok;
    }
}

// ---------------- convert + histogram fused ----------------
__global__ void k_convhist(const void* ei) {
    int e = blockIdx.x * blockDim.x + threadIdx.x;
    if (e >= EE) return;
    int s, d;
    if (g_is64) {
        const long long* p = (const long long*)ei;
        s = (int)p[e];
        d = (int)p[EE + e];
    } else {
        const int* p = (const int*)ei;
        s = p[e];
        d = p[EE + e];
    }
    g_src[e] = s;
    g_dstE[e] = d;
    if (s != d) atomicAdd(&g_deg[d], 1);  // original self-loops dropped (exp(-1e9-amax)==0)
}

// ---------------- scan ----------------
__global__ void k_scan1() {
    __shared__ int sh[1024];
    int tid = threadIdx.x;
    int i = blockIdx.x * 1024 + tid;
    int v = (i < NN) ? g_deg[i] : 0;
    sh[tid] = v;
    __syncthreads();
    for (int o = 1; o < 1024; o <<= 1) {
        int t = (tid >= o) ? sh[tid - o] : 0;
        __syncthreads();
        sh[tid] += t;
        __syncthreads();
    }
    if (i < NN) g_rowptr[i] = sh[tid] - v;
    if (tid == 1023) g_bsum[blockIdx.x] = sh[1023];
}

__global__ void k_scan23() {
    __shared__ int sh[128];
    int tid = threadIdx.x;
    int i = blockIdx.x * 256 + tid;
    if (tid < 128) sh[tid] = (tid < NB) ? g_bsum[tid] : 0;
    __syncthreads();
    for (int o = 1; o < 128; o <<= 1) {
        int t = (tid >= o && tid < 128) ? sh[tid - o] : 0;
        __syncthreads();
        if (tid < 128) sh[tid] += t;
        __syncthreads();
    }
    if (i < NN) {
        int blk = i >> 10;
        int exc = blk ? sh[blk - 1] : 0;
        int r = g_rowptr[i] + exc;
        g_rowptr[i] = r;
        g_cursor[i] = r;
    }
    if (blockIdx.x == 0 && tid == 0) g_rowptr[NN] = sh[127];
}

__global__ void k_scatter() {
    int e = blockIdx.x * blockDim.x + threadIdx.x;
    if (e >= EE + NN) return;
    if (e < EE) {
        int s = g_src[e], d = g_dstE[e];
        if (s != d) {
            int p = atomicAdd(&g_cursor[d], 1);
            g_col[p] = s;
        }
    } else {
        int n = e - EE;
        int p = atomicAdd(&g_cursor[n], 1);
        g_col[p] = n;
    }
}

// ---------------- tiled FFMA GEMM + fused attention-dot epilogue ----------------
template <int K, int NOUT, int MROWS, int TX, int HEADS>
__global__ __launch_bounds__(256) void k_gemm(const float* __restrict__ A,
                                              const float* __restrict__ W,
                                              const float* __restrict__ att,
                                              int use_g_act) {
    __shared__ float Ws[K * NOUT];
    __shared__ float As[MROWS][36];
    const float* Ap = use_g_act ? (const float*)g_act : A;

    int tid = threadIdx.x;
    int row0 = blockIdx.x * MROWS;

    for (int i = tid; i < K * NOUT / 4; i += 256)
        ((float4*)Ws)[i] = ((const float4*)W)[i];

    int tx = tid % TX, ty = tid / TX;
    int r0 = ty * 4, c0 = tx * 4;
    float acc[4][4];
#pragma unroll
    for (int i = 0; i < 4; i++)
#pragma unroll
        for (int j = 0; j < 4; j++) acc[i][j] = 0.f;

    for (int kb = 0; kb < K; kb += 32) {
        __syncthreads();
        for (int f = tid; f < MROWS * 8; f += 256) {
            int r = f >> 3, c4 = f & 7;
            float4 v = make_float4(0.f, 0.f, 0.f, 0.f);
            if (row0 + r < NN)
                v = *(const float4*)&Ap[(row0 + r) * K + kb + c4 * 4];
            *(float4*)&As[r][c4 * 4] = v;
        }
        __syncthreads();
#pragma unroll
        for (int kk = 0; kk < 32; kk++) {
            float a0 = As[r0 + 0][kk];
            float a1 = As[r0 + 1][kk];
            float a2 = As[r0 + 2][kk];
            float a3 = As[r0 + 3][kk];
            float4 b = *(float4*)&Ws[(kb + kk) * NOUT + c0];
            acc[0][0] += a0 * b.x; acc[0][1] += a0 * b.y; acc[0][2] += a0 * b.z; acc[0][3] += a0 * b.w;
            acc[1][0] += a1 * b.x; acc[1][1] += a1 * b.y; acc[1][2] += a1 * b.z; acc[1][3] += a1 * b.w;
            acc[2][0] += a2 * b.x; acc[2][1] += a2 * b.y; acc[2][2] += a2 * b.z; acc[2][3] += a2 * b.w;
            acc[3][0] += a3 * b.x; acc[3][1] += a3 * b.y; acc[3][2] += a3 * b.z; acc[3][3] += a3 * b.w;
        }
    }
    // store h as fp16
#pragma unroll
    for (int i = 0; i < 4; i++) {
        int r = row0 + r0 + i;
        if (r < NN) {
            __half2 lo = __floats2half2_rn(acc[i][0], acc[i][1]);
            __half2 hi = __floats2half2_rn(acc[i][2], acc[i][3]);
            __half2* dst = (__half2*)&g_h16[r * NOUT + c0];
            dst[0] = lo;
            dst[1] = hi;
        }
    }

    // ---- fused attention dots ----
    constexpr int CPH = NOUT / HEADS;
    constexpr int TPH = CPH / 4;
    float wd[4], wsrc[4];
#pragma unroll
    for (int j = 0; j < 4; j++) {
        int col = c0 + j;
        int h = col / CPH, c = col % CPH;
        wd[j]   = att[h * (2 * CPH) + c];
        wsrc[j] = att[h * (2 * CPH) + CPH + c];
    }
    __syncthreads();  // smem tiles dead; reuse As (dst partials) + Ws (src partials)
#pragma unroll
    for (int i = 0; i < 4; i++) {
        float pd = acc[i][0] * wd[0] + acc[i][1] * wd[1] + acc[i][2] * wd[2] + acc[i][3] * wd[3];
        float ps = acc[i][0] * wsrc[0] + acc[i][1] * wsrc[1] + acc[i][2] * wsrc[2] + acc[i][3] * wsrc[3];
        As[r0 + i][tx] = pd;
        Ws[(r0 + i) * TX + tx] = ps;
    }
    __syncthreads();
    for (int idx = tid; idx < MROWS * HEADS; idx += 256) {
        int r = idx / HEADS, h = idx % HEADS;
        float sd = 0.f, ss = 0.f;
#pragma unroll
        for (int q = 0; q < TPH; q++) {
            sd += As[r][h * TPH + q];
            ss += Ws[r * TX + h * TPH + q];
        }
        int row = row0 + r;
        if (row < NN) {
            g_adst[row * HEADS + h] = sd;
            g_asrc[row * HEADS + h] = ss;
        }
    }
}

__device__ __forceinline__ float leaky_exp(float a) {
    a = a > 0.f ? a : 0.2f * a;
    return __expf(a);
}

// ---------------- aggregate H=8: warp per node, shuffle-staged weights ----------------
// Phase A: lanes = (edge 0..3) x (head 0..7) -> ONE warp-MUFU per 4 edges.
// Phase B: shuffle-broadcast ids/weights, issue all 4 h-row gathers back-to-back.
// Padding edges clamp to a valid index with weight 0 -> zero branches in the body.
__global__ __launch_bounds__(256) void k_agg8(const float* __restrict__ bias, int do_elu) {
    int t = blockIdx.x * blockDim.x + threadIdx.x;
    int n = t >> 5, lane = t & 31;
    if (n >= NN) return;
    const unsigned full = 0xffffffffu;
    int start = g_rowptr[n], end = g_rowptr[n + 1];
    int hA = lane & 7;    // phase-A head
    int hB = lane >> 2;   // phase-B head (cols 2*lane, 2*lane+1)
    int eoff = lane >> 3; // phase-A edge slot 0..3

    float adstA = g_adst[n * 8 + hA];
    float2 acc = make_float2(0.f, 0.f);
    float dsum = 0.f;

    for (int base = start; base < end; base += 4) {
        int e = base + eoff;
        int valid = e < end;
        int ec = valid ? e : end - 1;          // clamp: always a real edge of this node
        int scol = g_col[ec];
        float ex = leaky_exp(adstA + g_asrc[scol * 8 + hA]);
        ex = valid ? ex : 0.f;

        int s0 = __shfl_sync(full, scol, 0);
        int s1 = __shfl_sync(full, scol, 8);
        int s2 = __shfl_sync(full, scol, 16);
        int s3 = __shfl_sync(full, scol, 24);
        float2 v0 = __half22float2(*(const __half2*)&g_h16[s0 * 64 + lane * 2]);
        float2 v1 = __half22float2(*(const __half2*)&g_h16[s1 * 64 + lane * 2]);
        float2 v2 = __half22float2(*(const __half2*)&g_h16[s2 * 64 + lane * 2]);
        float2 v3 = __half22float2(*(const __half2*)&g_h16[s3 * 64 + lane * 2]);
        float w0 = __shfl_sync(full, ex, hB);
        float w1 = __shfl_sync(full, ex, 8 + hB);
        float w2 = __shfl_sync(full, ex, 16 + hB);
        float w3 = __shfl_sync(full, ex, 24 + hB);
        acc.x += v0.x * w0 + v1.x * w1 + v2.x * w2 + v3.x * w3;
        acc.y += v0.y * w0 + v1.y * w1 + v2.y * w2 + v3.y * w3;
        dsum += (w0 + w1) + (w2 + w3);
    }
    float inv = 1.f / dsum;
    float o0 = acc.x * inv + bias[lane * 2];
    float o1 = acc.y * inv + bias[lane * 2 + 1];
    if (do_elu) {
        o0 = o0 > 0.f ? o0 : expm1f(o0);
        o1 = o1 > 0.f ? o1 : expm1f(o1);
    }
    *(float2*)&g_act[n * 64 + lane * 2] = make_float2(o0, o1);
}

// ---------------- aggregate H=1: warp per node, paired-edge fp16 gather (R5) ----------------
__global__ __launch_bounds__(256) void k_agg32(const float* __restrict__ bias,
                                               float* __restrict__ outp) {
    int t = blockIdx.x * blockDim.x + threadIdx.x;
    int n = t >> 5, lane = t & 31;
    if (n >= NN) return;
    const unsigned full = 0xffffffffu;
    int start = g_rowptr[n], end = g_rowptr[n + 1];
    int half = lane >> 4;
    int c2 = (lane & 15) * 2;

    float adst = g_adst[n];
    float2 acc = make_float2(0.f, 0.f);
    float dsum = 0.f;

    for (int base = start; base < end; base += 32) {
        int e = base + lane;
        float ex = 0.f;
        int scol = 0;
        if (e < end) {
            scol = g_col[e];
            float a = adst + g_asrc[scol];
            a = a > 0.f ? a : 0.2f * a;
            ex = __expf(a);
        }
        int cnt = min(32, end - base);
#pragma unroll 4
        for (int j2 = 0; j2 * 2 < cnt; j2++) {
            int j = j2 * 2 + half;
            int s = __shfl_sync(full, scol, j);
            float w = __shfl_sync(full, ex, j);
            if (j < cnt) {
                float2 hv = __half22float2(*(const __half2*)&g_h16[s * 32 + c2]);
                acc.x += hv.x * w;
                acc.y += hv.y * w;
                dsum += w;
            }
        }
    }
    acc.x += __shfl_xor_sync(full, acc.x, 16);
    acc.y += __shfl_xor_sync(full, acc.y, 16);
    dsum += __shfl_xor_sync(full, dsum, 16);
    if (lane < 16) {
        float inv = 1.f / dsum;
        outp[n * 32 + c2] = acc.x * inv + bias[c2];
        outp[n * 32 + c2 + 1] = acc.y * inv + bias[c2 + 1];
    }
}

// ---------------- launch ----------------
extern "C" void kernel_launch(void* const* d_in, const int* in_sizes, int n_in,
                              void* d_out, int out_size) {
    const float* x    = (const float*)d_in[0];
    const void*  ei   = d_in[1];
    const float* W1   = (const float*)d_in[2];
    const float* att1 = (const float*)d_in[3];
    const float* b1   = (const float*)d_in[4];
    const float* W2   = (const float*)d_in[5];
    const float* att2 = (const float*)d_in[6];
    const float* b2   = (const float*)d_in[7];
    const float* W3   = (const float*)d_in[8];
    const float* att3 = (const float*)d_in[9];
    const float* b3   = (const float*)d_in[10];
    float* out = (float*)d_out;

    const int TB = 256;
    const int warpGrid = (NN * 32 + TB - 1) / TB;

    // CSR build (dst layer-invariant)
    k_init<<<(NN + TB - 1) / TB, TB>>>(ei);
    k_convhist<<<(EE + TB - 1) / TB, TB>>>(ei);
    k_scan1<<<NB, 1024>>>();
    k_scan23<<<(NN + 255) / 256, 256>>>();
    k_scatter<<<(EE + NN + TB - 1) / TB, TB>>>();

    // Layer 1: 128 -> 8x8
    k_gemm<128, 64, 64, 16, 8><<<(NN + 63) / 64, TB>>>(x, W1, att1, 0);
    k_agg8<<<warpGrid, TB>>>(b1, 1);

    // Layer 2: 64 -> 8x8
    k_gemm<64, 64, 64, 16, 8><<<(NN + 63) / 64, TB>>>(nullptr, W2, att2, 1);
    k_agg8<<<warpGrid, TB>>>(b2, 1);

    // Layer 3: 64 -> 1x32
    k_gemm<64, 32, 128, 8, 1><<<(NN + 127) / 128, TB>>>(nullptr, W3, att3, 1);
    k_agg32<<<warpGrid, TB>>>(b3, out);
}

// round 8
// speedup vs baseline: 1.5937x; 1.0206x over previous
#include <cuda_runtime.h>
#include <cuda_fp16.h>

#define NN 100000
#define EE 1600000
#define NB 98  // (NN + 1023) / 1024

// ---------------- scratch (static device globals; no allocation) ----------------
__device__ int    g_is64;
__device__ int    g_src[EE];
__device__ int    g_dstE[EE];
__device__ int    g_deg[NN];
__device__ int    g_rowptr[NN + 1];
__device__ int    g_cursor[NN];
__device__ int    g_bsum[128];
__device__ int    g_col[EE + NN];
__device__ __half g_h16[NN * 64];
__device__ float  g_act[NN * 64];
__device__ float  g_adst[NN * 8];
__device__ float  g_asrc[NN * 8];

// ---------------- init: deg=1 (self-loop) + dtype detect ----------------
__global__ void k_init(const void* ei) {
    int i = blockIdx.x * blockDim.x + threadIdx.x;
    if (i < NN) g_deg[i] = 1;
    if (i == 0) {
        const long long* p = (const long long*)ei;
        int ok = 1;
        for (int k = 0; k < 8; k++) {
            long long v = p[k];
            if (v < 0 || v >= NN) ok = 0;
        }
        g_is64 = ok;
    }
}

// ---------------- convert + histogram fused ----------------
__global__ void k_convhist(const void* ei) {
    int e = blockIdx.x * blockDim.x + threadIdx.x;
    if (e >= EE) return;
    int s, d;
    if (g_is64) {
        const long long* p = (const long long*)ei;
        s = (int)p[e];
        d = (int)p[EE + e];
    } else {
        const int* p = (const int*)ei;
        s = p[e];
        d = p[EE + e];
    }
    g_src[e] = s;
    g_dstE[e] = d;
    if (s != d) atomicAdd(&g_deg[d], 1);  // original self-loops dropped (exp(-1e9-amax)==0)
}

// ---------------- scan ----------------
__global__ void k_scan1() {
    __shared__ int sh[1024];
    int tid = threadIdx.x;
    int i = blockIdx.x * 1024 + tid;
    int v = (i < NN) ? g_deg[i] : 0;
    sh[tid] = v;
    __syncthreads();
    for (int o = 1; o < 1024; o <<= 1) {
        int t = (tid >= o) ? sh[tid - o] : 0;
        __syncthreads();
        sh[tid] += t;
        __syncthreads();
    }
    if (i < NN) g_rowptr[i] = sh[tid] - v;
    if (tid == 1023) g_bsum[blockIdx.x] = sh[1023];
}

__global__ void k_scan23() {
    __shared__ int sh[128];
    int tid = threadIdx.x;
    int i = blockIdx.x * 256 + tid;
    if (tid < 128) sh[tid] = (tid < NB) ? g_bsum[tid] : 0;
    __syncthreads();
    for (int o = 1; o < 128; o <<= 1) {
        int t = (tid >= o && tid < 128) ? sh[tid - o] : 0;
        __syncthreads();
        if (tid < 128) sh[tid] += t;
        __syncthreads();
    }
    if (i < NN) {
        int blk = i >> 10;
        int exc = blk ? sh[blk - 1] : 0;
        int r = g_rowptr[i] + exc;
        g_rowptr[i] = r;
        g_cursor[i] = r;
    }
    if (blockIdx.x == 0 && tid == 0) g_rowptr[NN] = sh[127];
}

__global__ void k_scatter() {
    int e = blockIdx.x * blockDim.x + threadIdx.x;
    if (e >= EE + NN) return;
    if (e < EE) {
        int s = g_src[e], d = g_dstE[e];
        if (s != d) {
            int p = atomicAdd(&g_cursor[d], 1);
            g_col[p] = s;
        }
    } else {
        int n = e - EE;
        int p = atomicAdd(&g_cursor[n], 1);
        g_col[p] = n;
    }
}

// ---------------- tiled FFMA GEMM + fused attention-dot epilogue ----------------
template <int K, int NOUT, int MROWS, int TX, int HEADS>
__global__ __launch_bounds__(256) void k_gemm(const float* __restrict__ A,
                                              const float* __restrict__ W,
                                              const float* __restrict__ att,
                                              int use_g_act) {
    __shared__ float Ws[K * NOUT];
    __shared__ float As[MROWS][36];
    const float* Ap = use_g_act ? (const float*)g_act : A;

    int tid = threadIdx.x;
    int row0 = blockIdx.x * MROWS;

    for (int i = tid; i < K * NOUT / 4; i += 256)
        ((float4*)Ws)[i] = ((const float4*)W)[i];

    int tx = tid % TX, ty = tid / TX;
    int r0 = ty * 4, c0 = tx * 4;
    float acc[4][4];
#pragma unroll
    for (int i = 0; i < 4; i++)
#pragma unroll
        for (int j = 0; j < 4; j++) acc[i][j] = 0.f;

    for (int kb = 0; kb < K; kb += 32) {
        __syncthreads();
        for (int f = tid; f < MROWS * 8; f += 256) {
            int r = f >> 3, c4 = f & 7;
            float4 v = make_float4(0.f, 0.f, 0.f, 0.f);
            if (row0 + r < NN)
                v = *(const float4*)&Ap[(row0 + r) * K + kb + c4 * 4];
            *(float4*)&As[r][c4 * 4] = v;
        }
        __syncthreads();
#pragma unroll
        for (int kk = 0; kk < 32; kk++) {
            float a0 = As[r0 + 0][kk];
            float a1 = As[r0 + 1][kk];
            float a2 = As[r0 + 2][kk];
            float a3 = As[r0 + 3][kk];
            float4 b = *(float4*)&Ws[(kb + kk) * NOUT + c0];
            acc[0][0] += a0 * b.x; acc[0][1] += a0 * b.y; acc[0][2] += a0 * b.z; acc[0][3] += a0 * b.w;
            acc[1][0] += a1 * b.x; acc[1][1] += a1 * b.y; acc[1][2] += a1 * b.z; acc[1][3] += a1 * b.w;
            acc[2][0] += a2 * b.x; acc[2][1] += a2 * b.y; acc[2][2] += a2 * b.z; acc[2][3] += a2 * b.w;
            acc[3][0] += a3 * b.x; acc[3][1] += a3 * b.y; acc[3][2] += a3 * b.z; acc[3][3] += a3 * b.w;
        }
    }
    // store h as fp16
#pragma unroll
    for (int i = 0; i < 4; i++) {
        int r = row0 + r0 + i;
        if (r < NN) {
            __half2 lo = __floats2half2_rn(acc[i][0], acc[i][1]);
            __half2 hi = __floats2half2_rn(acc[i][2], acc[i][3]);
            __half2* dst = (__half2*)&g_h16[r * NOUT + c0];
            dst[0] = lo;
            dst[1] = hi;
        }
    }

    // ---- fused attention dots ----
    constexpr int CPH = NOUT / HEADS;
    constexpr int TPH = CPH / 4;
    float wd[4], wsrc[4];
#pragma unroll
    for (int j = 0; j < 4; j++) {
        int col = c0 + j;
        int h = col / CPH, c = col % CPH;
        wd[j]   = att[h * (2 * CPH) + c];
        wsrc[j] = att[h * (2 * CPH) + CPH + c];
    }
    __syncthreads();  // smem tiles dead; reuse As (dst partials) + Ws (src partials)
#pragma unroll
    for (int i = 0; i < 4; i++) {
        float pd = acc[i][0] * wd[0] + acc[i][1] * wd[1] + acc[i][2] * wd[2] + acc[i][3] * wd[3];
        float ps = acc[i][0] * wsrc[0] + acc[i][1] * wsrc[1] + acc[i][2] * wsrc[2] + acc[i][3] * wsrc[3];
        As[r0 + i][tx] = pd;
        Ws[(r0 + i) * TX + tx] = ps;
    }
    __syncthreads();
    for (int idx = tid; idx < MROWS * HEADS; idx += 256) {
        int r = idx / HEADS, h = idx % HEADS;
        float sd = 0.f, ss = 0.f;
#pragma unroll
        for (int q = 0; q < TPH; q++) {
            sd += As[r][h * TPH + q];
            ss += Ws[r * TX + h * TPH + q];
        }
        int row = row0 + r;
        if (row < NN) {
            g_adst[row * HEADS + h] = sd;
            g_asrc[row * HEADS + h] = ss;
        }
    }
}

__device__ __forceinline__ float leaky_exp(float a) {
    a = a > 0.f ? a : 0.2f * a;
    return __expf(a);
}

// ---------------- aggregate H=8: warp per node, 8-edge batches ----------------
// Phase A: lanes = (edge slot 0..3) x (head 0..7), TWO independent groups per
// iteration -> 2 warp-MUFU per 8 edges, ~12 loads in flight. Clamp+mask padding
// (weight 0, valid address) -> no tail loop, no branches in the body.
__global__ __launch_bounds__(256) void k_agg8(const float* __restrict__ bias, int do_elu) {
    int t = blockIdx.x * blockDim.x + threadIdx.x;
    int n = t >> 5, lane = t & 31;
    if (n >= NN) return;
    const unsigned full = 0xffffffffu;
    int start = g_rowptr[n], end = g_rowptr[n + 1];
    int hA = lane & 7;    // phase-A head
    int hB = lane >> 2;   // phase-B head (cols 2*lane, 2*lane+1)
    int eoff = lane >> 3; // phase-A edge slot 0..3

    float adstA = g_adst[n * 8 + hA];
    float2 acc = make_float2(0.f, 0.f);
    float dsum = 0.f;

    for (int base = start; base < end; base += 8) {
        int eA = base + eoff;
        int eB = eA + 4;
        int validA = eA < end;
        int validB = eB < end;
        int ecA = validA ? eA : end - 1;
        int ecB = validB ? eB : end - 1;
        int sA = g_col[ecA];
        int sB = g_col[ecB];
        float aA = g_asrc[sA * 8 + hA];
        float aB = g_asrc[sB * 8 + hA];

        int s0 = __shfl_sync(full, sA, 0);
        int s1 = __shfl_sync(full, sA, 8);
        int s2 = __shfl_sync(full, sA, 16);
        int s3 = __shfl_sync(full, sA, 24);
        int s4 = __shfl_sync(full, sB, 0);
        int s5 = __shfl_sync(full, sB, 8);
        int s6 = __shfl_sync(full, sB, 16);
        int s7 = __shfl_sync(full, sB, 24);
        float2 v0 = __half22float2(*(const __half2*)&g_h16[s0 * 64 + lane * 2]);
        float2 v1 = __half22float2(*(const __half2*)&g_h16[s1 * 64 + lane * 2]);
        float2 v2 = __half22float2(*(const __half2*)&g_h16[s2 * 64 + lane * 2]);
        float2 v3 = __half22float2(*(const __half2*)&g_h16[s3 * 64 + lane * 2]);
        float2 v4 = __half22float2(*(const __half2*)&g_h16[s4 * 64 + lane * 2]);
        float2 v5 = __half22float2(*(const __half2*)&g_h16[s5 * 64 + lane * 2]);
        float2 v6 = __half22float2(*(const __half2*)&g_h16[s6 * 64 + lane * 2]);
        float2 v7 = __half22float2(*(const __half2*)&g_h16[s7 * 64 + lane * 2]);

        float exA = leaky_exp(adstA + aA);
        float exB = leaky_exp(adstA + aB);
        exA = validA ? exA : 0.f;
        exB = validB ? exB : 0.f;

        float w0 = __shfl_sync(full, exA, hB);
        float w1 = __shfl_sync(full, exA, 8 + hB);
        float w2 = __shfl_sync(full, exA, 16 + hB);
        float w3 = __shfl_sync(full, exA, 24 + hB);
        float w4 = __shfl_sync(full, exB, hB);
        float w5 = __shfl_sync(full, exB, 8 + hB);
        float w6 = __shfl_sync(full, exB, 16 + hB);
        float w7 = __shfl_sync(full, exB, 24 + hB);

        acc.x += v0.x * w0 + v1.x * w1 + v2.x * w2 + v3.x * w3;
        acc.x += v4.x * w4 + v5.x * w5 + v6.x * w6 + v7.x * w7;
        acc.y += v0.y * w0 + v1.y * w1 + v2.y * w2 + v3.y * w3;
        acc.y += v4.y * w4 + v5.y * w5 + v6.y * w6 + v7.y * w7;
        dsum += ((w0 + w1) + (w2 + w3)) + ((w4 + w5) + (w6 + w7));
    }
    float inv = 1.f / dsum;
    float o0 = acc.x * inv + bias[lane * 2];
    float o1 = acc.y * inv + bias[lane * 2 + 1];
    if (do_elu) {
        o0 = o0 > 0.f ? o0 : expm1f(o0);
        o1 = o1 > 0.f ? o1 : expm1f(o1);
    }
    *(float2*)&g_act[n * 64 + lane * 2] = make_float2(o0, o1);
}

// ---------------- aggregate H=1: warp per node, paired-edge fp16 gather ----------------
__global__ __launch_bounds__(256) void k_agg32(const float* __restrict__ bias,
                                               float* __restrict__ outp) {
    int t = blockIdx.x * blockDim.x + threadIdx.x;
    int n = t >> 5, lane = t & 31;
    if (n >= NN) return;
    const unsigned full = 0xffffffffu;
    int start = g_rowptr[n], end = g_rowptr[n + 1];
    int half = lane >> 4;
    int c2 = (lane & 15) * 2;

    float adst = g_adst[n];
    float2 acc = make_float2(0.f, 0.f);
    float dsum = 0.f;

    for (int base = start; base < end; base += 32) {
        int e = base + lane;
        float ex = 0.f;
        int scol = 0;
        if (e < end) {
            scol = g_col[e];
            float a = adst + g_asrc[scol];
            a = a > 0.f ? a : 0.2f * a;
            ex = __expf(a);
        }
        int cnt = min(32, end - base);
#pragma unroll 4
        for (int j2 = 0; j2 * 2 < cnt; j2++) {
            int j = j2 * 2 + half;
            int s = __shfl_sync(full, scol, j);
            float w = __shfl_sync(full, ex, j);
            if (j < cnt) {
                float2 hv = __half22float2(*(const __half2*)&g_h16[s * 32 + c2]);
                acc.x += hv.x * w;
                acc.y += hv.y * w;
                dsum += w;
            }
        }
    }
    acc.x += __shfl_xor_sync(full, acc.x, 16);
    acc.y += __shfl_xor_sync(full, acc.y, 16);
    dsum += __shfl_xor_sync(full, dsum, 16);
    if (lane < 16) {
        float inv = 1.f / dsum;
        outp[n * 32 + c2] = acc.x * inv + bias[c2];
        outp[n * 32 + c2 + 1] = acc.y * inv + bias[c2 + 1];
    }
}

// ---------------- launch ----------------
extern "C" void kernel_launch(void* const* d_in, const int* in_sizes, int n_in,
                              void* d_out, int out_size) {
    const float* x    = (const float*)d_in[0];
    const void*  ei   = d_in[1];
    const float* W1   = (const float*)d_in[2];
    const float* att1 = (const float*)d_in[3];
    const float* b1   = (const float*)d_in[4];
    const float* W2   = (const float*)d_in[5];
    const float* att2 = (const float*)d_in[6];
    const float* b2   = (const float*)d_in[7];
    const float* W3   = (const float*)d_in[8];
    const float* att3 = (const float*)d_in[9];
    const float* b3   = (const float*)d_in[10];
    float* out = (float*)d_out;

    const int TB = 256;
    const int warpGrid = (NN * 32 + TB - 1) / TB;

    // CSR build (dst layer-invariant)
    k_init<<<(NN + TB - 1) / TB, TB>>>(ei);
    k_convhist<<<(EE + TB - 1) / TB, TB>>>(ei);
    k_scan1<<<NB, 1024>>>();
    k_scan23<<<(NN + 255) / 256, 256>>>();
    k_scatter<<<(EE + NN + TB - 1) / TB, TB>>>();

    // Layer 1: 128 -> 8x8
    k_gemm<128, 64, 64, 16, 8><<<(NN + 63) / 64, TB>>>(x, W1, att1, 0);
    k_agg8<<<warpGrid, TB>>>(b1, 1);

    // Layer 2: 64 -> 8x8
    k_gemm<64, 64, 64, 16, 8><<<(NN + 63) / 64, TB>>>(nullptr, W2, att2, 1);
    k_agg8<<<warpGrid, TB>>>(b2, 1);

    // Layer 3: 64 -> 1x32
    k_gemm<64, 32, 128, 8, 1><<<(NN + 127) / 128, TB>>>(nullptr, W3, att3, 1);
    k_agg32<<<warpGrid, TB>>>(b3, out);
}

// round 9
// speedup vs baseline: 1.9040x; 1.1946x over previous
#include <cuda_runtime.h>
#include <cuda_fp16.h>
#include <mma.h>

using namespace nvcuda;

#define NN 100000
#define EE 1600000
#define NB 98  // (NN + 1023) / 1024

// ---------------- scratch (static device globals; no allocation) ----------------
__device__ int    g_is64;
__device__ int    g_src[EE];
__device__ int    g_dstE[EE];
__device__ int    g_deg[NN];
__device__ int    g_rowptr[NN + 1];
__device__ int    g_cursor[NN];
__device__ int    g_bsum[128];
__device__ int    g_col[EE + NN];
__device__ __half g_h16[NN * 64];
__device__ __half g_act16[NN * 64];
__device__ float  g_adst[NN * 8];
__device__ float  g_asrc[NN * 8];

// ---------------- init: deg=1 (self-loop) + dtype detect ----------------
__global__ void k_init(const void* ei) {
    int i = blockIdx.x * blockDim.x + threadIdx.x;
    if (i < NN) g_deg[i] = 1;
    if (i == 0) {
        const long long* p = (const long long*)ei;
        int ok = 1;
        for (int k = 0; k < 8; k++) {
            long long v = p[k];
            if (v < 0 || v >= NN) ok = 0;
        }
        g_is64 = ok;
    }
}

// ---------------- convert + histogram fused ----------------
__global__ void k_convhist(const void* ei) {
    int e = blockIdx.x * blockDim.x + threadIdx.x;
    if (e >= EE) return;
    int s, d;
    if (g_is64) {
        const long long* p = (const long long*)ei;
        s = (int)p[e];
        d = (int)p[EE + e];
    } else {
        const int* p = (const int*)ei;
        s = p[e];
        d = p[EE + e];
    }
    g_src[e] = s;
    g_dstE[e] = d;
    if (s != d) atomicAdd(&g_deg[d], 1);  // original self-loops dropped (exp(-1e9-amax)==0)
}

// ---------------- scan ----------------
__global__ void k_scan1() {
    __shared__ int sh[1024];
    int tid = threadIdx.x;
    int i = blockIdx.x * 1024 + tid;
    int v = (i < NN) ? g_deg[i] : 0;
    sh[tid] = v;
    __syncthreads();
    for (int o = 1; o < 1024; o <<= 1) {
        int t = (tid >= o) ? sh[tid - o] : 0;
        __syncthreads();
        sh[tid] += t;
        __syncthreads();
    }
    if (i < NN) g_rowptr[i] = sh[tid] - v;
    if (tid == 1023) g_bsum[blockIdx.x] = sh[1023];
}

__global__ void k_scan23() {
    __shared__ int sh[128];
    int tid = threadIdx.x;
    int i = blockIdx.x * 256 + tid;
    if (tid < 128) sh[tid] = (tid < NB) ? g_bsum[tid] : 0;
    __syncthreads();
    for (int o = 1; o < 128; o <<= 1) {
        int t = (tid >= o && tid < 128) ? sh[tid - o] : 0;
        __syncthreads();
        if (tid < 128) sh[tid] += t;
        __syncthreads();
    }
    if (i < NN) {
        int blk = i >> 10;
        int exc = blk ? sh[blk - 1] : 0;
        int r = g_rowptr[i] + exc;
        g_rowptr[i] = r;
        g_cursor[i] = r;
    }
    if (blockIdx.x == 0 && tid == 0) g_rowptr[NN] = sh[127];
}

__global__ void k_scatter() {
    int e = blockIdx.x * blockDim.x + threadIdx.x;
    if (e >= EE + NN) return;
    if (e < EE) {
        int s = g_src[e], d = g_dstE[e];
        if (s != d) {
            int p = atomicAdd(&g_cursor[d], 1);
            g_col[p] = s;
        }
    } else {
        int n = e - EE;
        int p = atomicAdd(&g_cursor[n], 1);
        g_col[p] = n;
    }
}

// ---------------- wmma tensor-core GEMM + fused attention-dot epilogue ----------------
// C[N,NOUT] = A[N,K] @ W[K,NOUT]. A/W fp16 operands, fp32 accumulate.
// 64-row M-tile, 8 warps: warp w -> row band (w>>1)*16, col half (w&1)*(NOUT/2).
template <int K, int NOUT, int HEADS, bool HALF_A>
__global__ __launch_bounds__(256) void k_gemm_wmma(const float* __restrict__ Af,
                                                   const float* __restrict__ W,
                                                   const float* __restrict__ att) {
    constexpr int LDA = K + 8;
    constexpr int LDB = NOUT + 8;
    constexpr int LDC = NOUT + 8;
    constexpr int AB_BYTES = 64 * LDA * 2 + K * LDB * 2;
    constexpr int C_BYTES = 64 * LDC * 4;
    constexpr int SM_BYTES = AB_BYTES > C_BYTES ? AB_BYTES : C_BYTES;
    __shared__ __align__(16) char smem[SM_BYTES];
    __half (*Asm)[LDA] = reinterpret_cast<__half (*)[LDA]>(smem);
    __half (*Bsm)[LDB] = reinterpret_cast<__half (*)[LDB]>(smem + 64 * LDA * 2);
    float  (*Csm)[LDC] = reinterpret_cast<float (*)[LDC]>(smem);

    int tid = threadIdx.x;
    int w = tid >> 5;
    int row0 = blockIdx.x * 64;

    // load W -> fp16 smem
    for (int i = tid; i < K * NOUT / 4; i += 256) {
        int r = i / (NOUT / 4), c4 = i % (NOUT / 4);
        float4 v = ((const float4*)W)[i];
        __half2* dst = (__half2*)&Bsm[r][c4 * 4];
        dst[0] = __floats2half2_rn(v.x, v.y);
        dst[1] = __floats2half2_rn(v.z, v.w);
    }
    // load A -> fp16 smem
    if (HALF_A) {
        for (int i = tid; i < 64 * K / 8; i += 256) {
            int r = i / (K / 8), c8 = i % (K / 8);
            float4 v = make_float4(0.f, 0.f, 0.f, 0.f);
            if (row0 + r < NN)
                v = *(const float4*)&g_act16[(row0 + r) * K + c8 * 8];
            *(float4*)&Asm[r][c8 * 8] = v;
        }
    } else {
        for (int i = tid; i < 64 * K / 4; i += 256) {
            int r = i / (K / 4), c4 = i % (K / 4);
            float4 v = make_float4(0.f, 0.f, 0.f, 0.f);
            if (row0 + r < NN)
                v = *(const float4*)&Af[(row0 + r) * K + c4 * 4];
            __half2* dst = (__half2*)&Asm[r][c4 * 4];
            dst[0] = __floats2half2_rn(v.x, v.y);
            dst[1] = __floats2half2_rn(v.z, v.w);
        }
    }
    __syncthreads();

    constexpr int CFRAGS = NOUT / 32;  // 2 for NOUT=64, 1 for NOUT=32
    int rb = (w >> 1) * 16;
    int col0 = (w & 1) * (NOUT / 2);

    wmma::fragment<wmma::accumulator, 16, 16, 16, float> cfrag[CFRAGS];
#pragma unroll
    for (int j = 0; j < CFRAGS; j++) wmma::fill_fragment(cfrag[j], 0.f);

#pragma unroll
    for (int kk = 0; kk < K / 16; kk++) {
        wmma::fragment<wmma::matrix_a, 16, 16, 16, __half, wmma::row_major> afrag;
        wmma::load_matrix_sync(afrag, &Asm[rb][kk * 16], LDA);
#pragma unroll
        for (int j = 0; j < CFRAGS; j++) {
            wmma::fragment<wmma::matrix_b, 16, 16, 16, __half, wmma::row_major> bfrag;
            wmma::load_matrix_sync(bfrag, &Bsm[kk * 16][col0 + 16 * j], LDB);
            wmma::mma_sync(cfrag[j], afrag, bfrag, cfrag[j]);
        }
    }
    __syncthreads();  // A/B smem dead; Csm aliases it
#pragma unroll
    for (int j = 0; j < CFRAGS; j++)
        wmma::store_matrix_sync(&Csm[rb][col0 + 16 * j], cfrag[j], LDC, wmma::mem_row_major);
    __syncthreads();

    // store h as fp16
    for (int i = tid; i < 64 * NOUT / 2; i += 256) {
        int r = i / (NOUT / 2), c2 = i % (NOUT / 2);
        if (row0 + r < NN)
            *(__half2*)&g_h16[(row0 + r) * NOUT + c2 * 2] =
                __floats2half2_rn(Csm[r][c2 * 2], Csm[r][c2 * 2 + 1]);
    }
    // attention dots from fp32 C
    constexpr int CPH = NOUT / HEADS;
    for (int idx = tid; idx < 64 * HEADS; idx += 256) {
        int r = idx / HEADS, h = idx % HEADS;
        float sd = 0.f, ss = 0.f;
#pragma unroll
        for (int c = 0; c < CPH; c++) {
            float v = Csm[r][h * CPH + c];
            sd += v * att[h * (2 * CPH) + c];
            ss += v * att[h * (2 * CPH) + CPH + c];
        }
        int row = row0 + r;
        if (row < NN) {
            g_adst[row * HEADS + h] = sd;
            g_asrc[row * HEADS + h] = ss;
        }
    }
}

__device__ __forceinline__ float leaky_exp(float a) {
    a = a > 0.f ? a : 0.2f * a;
    return __expf(a);
}

// ---------------- aggregate H=8: warp per node, 8-edge batches ----------------
__global__ __launch_bounds__(256) void k_agg8(const float* __restrict__ bias, int do_elu) {
    int t = blockIdx.x * blockDim.x + threadIdx.x;
    int n = t >> 5, lane = t & 31;
    if (n >= NN) return;
    const unsigned full = 0xffffffffu;
    int start = g_rowptr[n], end = g_rowptr[n + 1];
    int hA = lane & 7;
    int hB = lane >> 2;
    int eoff = lane >> 3;

    float adstA = g_adst[n * 8 + hA];
    float2 acc = make_float2(0.f, 0.f);
    float dsum = 0.f;

    for (int base = start; base < end; base += 8) {
        int eA = base + eoff;
        int eB = eA + 4;
        int validA = eA < end;
        int validB = eB < end;
        int ecA = validA ? eA : end - 1;
        int ecB = validB ? eB : end - 1;
        int sA = g_col[ecA];
        int sB = g_col[ecB];
        float aA = g_asrc[sA * 8 + hA];
        float aB = g_asrc[sB * 8 + hA];

        int s0 = __shfl_sync(full, sA, 0);
        int s1 = __shfl_sync(full, sA, 8);
        int s2 = __shfl_sync(full, sA, 16);
        int s3 = __shfl_sync(full, sA, 24);
        int s4 = __shfl_sync(full, sB, 0);
        int s5 = __shfl_sync(full, sB, 8);
        int s6 = __shfl_sync(full, sB, 16);
        int s7 = __shfl_sync(full, sB, 24);
        float2 v0 = __half22float2(*(const __half2*)&g_h16[s0 * 64 + lane * 2]);
        float2 v1 = __half22float2(*(const __half2*)&g_h16[s1 * 64 + lane * 2]);
        float2 v2 = __half22float2(*(const __half2*)&g_h16[s2 * 64 + lane * 2]);
        float2 v3 = __half22float2(*(const __half2*)&g_h16[s3 * 64 + lane * 2]);
        float2 v4 = __half22float2(*(const __half2*)&g_h16[s4 * 64 + lane * 2]);
        float2 v5 = __half22float2(*(const __half2*)&g_h16[s5 * 64 + lane * 2]);
        float2 v6 = __half22float2(*(const __half2*)&g_h16[s6 * 64 + lane * 2]);
        float2 v7 = __half22float2(*(const __half2*)&g_h16[s7 * 64 + lane * 2]);

        float exA = leaky_exp(adstA + aA);
        float exB = leaky_exp(adstA + aB);
        exA = validA ? exA : 0.f;
        exB = validB ? exB : 0.f;

        float w0 = __shfl_sync(full, exA, hB);
        float w1 = __shfl_sync(full, exA, 8 + hB);
        float w2 = __shfl_sync(full, exA, 16 + hB);
        float w3 = __shfl_sync(full, exA, 24 + hB);
        float w4 = __shfl_sync(full, exB, hB);
        float w5 = __shfl_sync(full, exB, 8 + hB);
        float w6 = __shfl_sync(full, exB, 16 + hB);
        float w7 = __shfl_sync(full, exB, 24 + hB);

        acc.x += v0.x * w0 + v1.x * w1 + v2.x * w2 + v3.x * w3;
        acc.x += v4.x * w4 + v5.x * w5 + v6.x * w6 + v7.x * w7;
        acc.y += v0.y * w0 + v1.y * w1 + v2.y * w2 + v3.y * w3;
        acc.y += v4.y * w4 + v5.y * w5 + v6.y * w6 + v7.y * w7;
        dsum += ((w0 + w1) + (w2 + w3)) + ((w4 + w5) + (w6 + w7));
    }
    float inv = 1.f / dsum;
    float o0 = acc.x * inv + bias[lane * 2];
    float o1 = acc.y * inv + bias[lane * 2 + 1];
    if (do_elu) {
        o0 = o0 > 0.f ? o0 : expm1f(o0);
        o1 = o1 > 0.f ? o1 : expm1f(o1);
    }
    *(__half2*)&g_act16[n * 64 + lane * 2] = __floats2half2_rn(o0, o1);
}

// ---------------- aggregate H=1: warp per node, paired-edge fp16 gather ----------------
__global__ __launch_bounds__(256) void k_agg32(const float* __restrict__ bias,
                                               float* __restrict__ outp) {
    int t = blockIdx.x * blockDim.x + threadIdx.x;
    int n = t >> 5, lane = t & 31;
    if (n >= NN) return;
    const unsigned full = 0xffffffffu;
    int start = g_rowptr[n], end = g_rowptr[n + 1];
    int half = lane >> 4;
    int c2 = (lane & 15) * 2;

    float adst = g_adst[n];
    float2 acc = make_float2(0.f, 0.f);
    float dsum = 0.f;

    for (int base = start; base < end; base += 32) {
        int e = base + lane;
        float ex = 0.f;
        int scol = 0;
        if (e < end) {
            scol = g_col[e];
            float a = adst + g_asrc[scol];
            a = a > 0.f ? a : 0.2f * a;
            ex = __expf(a);
        }
        int cnt = min(32, end - base);
#pragma unroll 4
        for (int j2 = 0; j2 * 2 < cnt; j2++) {
            int j = j2 * 2 + half;
            int s = __shfl_sync(full, scol, j);
            float w = __shfl_sync(full, ex, j);
            if (j < cnt) {
                float2 hv = __half22float2(*(const __half2*)&g_h16[s * 32 + c2]);
                acc.x += hv.x * w;
                acc.y += hv.y * w;
                dsum += w;
            }
        }
    }
    acc.x += __shfl_xor_sync(full, acc.x, 16);
    acc.y += __shfl_xor_sync(full, acc.y, 16);
    dsum += __shfl_xor_sync(full, dsum, 16);
    if (lane < 16) {
        float inv = 1.f / dsum;
        outp[n * 32 + c2] = acc.x * inv + bias[c2];
        outp[n * 32 + c2 + 1] = acc.y * inv + bias[c2 + 1];
    }
}

// ---------------- launch ----------------
extern "C" void kernel_launch(void* const* d_in, const int* in_sizes, int n_in,
                              void* d_out, int out_size) {
    const float* x    = (const float*)d_in[0];
    const void*  ei   = d_in[1];
    const float* W1   = (const float*)d_in[2];
    const float* att1 = (const float*)d_in[3];
    const float* b1   = (const float*)d_in[4];
    const float* W2   = (const float*)d_in[5];
    const float* att2 = (const float*)d_in[6];
    const float* b2   = (const float*)d_in[7];
    const float* W3   = (const float*)d_in[8];
    const float* att3 = (const float*)d_in[9];
    const float* b3   = (const float*)d_in[10];
    float* out = (float*)d_out;

    const int TB = 256;
    const int warpGrid = (NN * 32 + TB - 1) / TB;
    const int gemmGrid = (NN + 63) / 64;

    // CSR build (dst layer-invariant)
    k_init<<<(NN + TB - 1) / TB, TB>>>(ei);
    k_convhist<<<(EE + TB - 1) / TB, TB>>>(ei);
    k_scan1<<<NB, 1024>>>();
    k_scan23<<<(NN + 255) / 256, 256>>>();
    k_scatter<<<(EE + NN + TB - 1) / TB, TB>>>();

    // Layer 1: 128 -> 8x8
    k_gemm_wmma<128, 64, 8, false><<<gemmGrid, TB>>>(x, W1, att1);
    k_agg8<<<warpGrid, TB>>>(b1, 1);

    // Layer 2: 64 -> 8x8
    k_gemm_wmma<64, 64, 8, true><<<gemmGrid, TB>>>(nullptr, W2, att2);
    k_agg8<<<warpGrid, TB>>>(b2, 1);

    // Layer 3: 64 -> 1x32
    k_gemm_wmma<64, 32, 1, true><<<gemmGrid, TB>>>(nullptr, W3, att3);
    k_agg32<<<warpGrid, TB>>>(b3, out);
}

// round 10
// speedup vs baseline: 1.9360x; 1.0169x over previous
#include <cuda_runtime.h>
#include <cuda_fp16.h>
#include <mma.h>

using namespace nvcuda;

#define NN 100000
#define EE 1600000
#define NB 98  // (NN + 1023) / 1024

// ---------------- scratch (static device globals; no allocation) ----------------
__device__ int    g_src[EE];
__device__ int    g_dstE[EE];
__device__ int    g_deg[NN];      // zero-init at load; re-zeroed by k_scan23 each call
__device__ int    g_rowptr[NN + 1];
__device__ int    g_cursor[NN];
__device__ int    g_bsum[128];
__device__ int    g_col[EE + NN];
__device__ __half g_h16[NN * 64];
__device__ __half g_act16[NN * 64];
__device__ float  g_adst[NN * 8];
__device__ float  g_asrc[NN * 8];

// ---------------- convert + histogram fused (is64 detected inline) ----------------
__global__ void k_convhist(const void* ei) {
    int e = blockIdx.x * blockDim.x + threadIdx.x;
    if (e >= EE) return;
    // dtype sniff: int64 indices in range -> is64; 8 loads from one cached line
    const long long* p64 = (const long long*)ei;
    int is64 = 1;
#pragma unroll
    for (int k = 0; k < 8; k++) {
        long long v = p64[k];
        if (v < 0 || v >= NN) is64 = 0;
    }
    int s, d;
    if (is64) {
        s = (int)p64[e];
        d = (int)p64[EE + e];
    } else {
        const int* p = (const int*)ei;
        s = p[e];
        d = p[EE + e];
    }
    g_src[e] = s;
    g_dstE[e] = d;
    if (s != d) atomicAdd(&g_deg[d], 1);  // original self-loops dropped (exp(-1e9-amax)==0)
}

// ---------------- scan (self-loop +1 folded in) ----------------
__global__ void k_scan1() {
    __shared__ int sh[1024];
    int tid = threadIdx.x;
    int i = blockIdx.x * 1024 + tid;
    int v = (i < NN) ? g_deg[i] + 1 : 0;  // +1 = appended self-loop
    sh[tid] = v;
    __syncthreads();
    for (int o = 1; o < 1024; o <<= 1) {
        int t = (tid >= o) ? sh[tid - o] : 0;
        __syncthreads();
        sh[tid] += t;
        __syncthreads();
    }
    if (i < NN) g_rowptr[i] = sh[tid] - v;
    if (tid == 1023) g_bsum[blockIdx.x] = sh[1023];
}

__global__ void k_scan23() {
    __shared__ int sh[128];
    int tid = threadIdx.x;
    int i = blockIdx.x * 256 + tid;
    if (tid < 128) sh[tid] = (tid < NB) ? g_bsum[tid] : 0;
    __syncthreads();
    for (int o = 1; o < 128; o <<= 1) {
        int t = (tid >= o && tid < 128) ? sh[tid - o] : 0;
        __syncthreads();
        if (tid < 128) sh[tid] += t;
        __syncthreads();
    }
    if (i < NN) {
        int blk = i >> 10;
        int exc = blk ? sh[blk - 1] : 0;
        int r = g_rowptr[i] + exc;
        g_rowptr[i] = r;
        g_cursor[i] = r;
        g_deg[i] = 0;  // reset for next call (deg fully consumed by scan1)
    }
    if (blockIdx.x == 0 && tid == 0) g_rowptr[NN] = sh[127];
}

__global__ void k_scatter() {
    int e = blockIdx.x * blockDim.x + threadIdx.x;
    if (e >= EE + NN) return;
    if (e < EE) {
        int s = g_src[e], d = g_dstE[e];
        if (s != d) {
            int p = atomicAdd(&g_cursor[d], 1);
            g_col[p] = s;
        }
    } else {
        int n = e - EE;
        int p = atomicAdd(&g_cursor[n], 1);
        g_col[p] = n;
    }
}

// ---------------- wmma tensor-core GEMM + fused attention-dot epilogue ----------------
template <int K, int NOUT, int HEADS, bool HALF_A>
__global__ __launch_bounds__(256) void k_gemm_wmma(const float* __restrict__ Af,
                                                   const float* __restrict__ W,
                                                   const float* __restrict__ att) {
    constexpr int LDA = K + 8;
    constexpr int LDB = NOUT + 8;
    constexpr int LDC = NOUT + 8;
    constexpr int AB_BYTES = 64 * LDA * 2 + K * LDB * 2;
    constexpr int C_BYTES = 64 * LDC * 4;
    constexpr int SM_BYTES = AB_BYTES > C_BYTES ? AB_BYTES : C_BYTES;
    __shared__ __align__(16) char smem[SM_BYTES];
    __half (*Asm)[LDA] = reinterpret_cast<__half (*)[LDA]>(smem);
    __half (*Bsm)[LDB] = reinterpret_cast<__half (*)[LDB]>(smem + 64 * LDA * 2);
    float  (*Csm)[LDC] = reinterpret_cast<float (*)[LDC]>(smem);

    int tid = threadIdx.x;
    int w = tid >> 5;
    int row0 = blockIdx.x * 64;

    for (int i = tid; i < K * NOUT / 4; i += 256) {
        int r = i / (NOUT / 4), c4 = i % (NOUT / 4);
        float4 v = ((const float4*)W)[i];
        __half2* dst = (__half2*)&Bsm[r][c4 * 4];
        dst[0] = __floats2half2_rn(v.x, v.y);
        dst[1] = __floats2half2_rn(v.z, v.w);
    }
    if (HALF_A) {
        for (int i = tid; i < 64 * K / 8; i += 256) {
            int r = i / (K / 8), c8 = i % (K / 8);
            float4 v = make_float4(0.f, 0.f, 0.f, 0.f);
            if (row0 + r < NN)
                v = *(const float4*)&g_act16[(row0 + r) * K + c8 * 8];
            *(float4*)&Asm[r][c8 * 8] = v;
        }
    } else {
        for (int i = tid; i < 64 * K / 4; i += 256) {
            int r = i / (K / 4), c4 = i % (K / 4);
            float4 v = make_float4(0.f, 0.f, 0.f, 0.f);
            if (row0 + r < NN)
                v = *(const float4*)&Af[(row0 + r) * K + c4 * 4];
            __half2* dst = (__half2*)&Asm[r][c4 * 4];
            dst[0] = __floats2half2_rn(v.x, v.y);
            dst[1] = __floats2half2_rn(v.z, v.w);
        }
    }
    __syncthreads();

    constexpr int CFRAGS = NOUT / 32;
    int rb = (w >> 1) * 16;
    int col0 = (w & 1) * (NOUT / 2);

    wmma::fragment<wmma::accumulator, 16, 16, 16, float> cfrag[CFRAGS];
#pragma unroll
    for (int j = 0; j < CFRAGS; j++) wmma::fill_fragment(cfrag[j], 0.f);

#pragma unroll
    for (int kk = 0; kk < K / 16; kk++) {
        wmma::fragment<wmma::matrix_a, 16, 16, 16, __half, wmma::row_major> afrag;
        wmma::load_matrix_sync(afrag, &Asm[rb][kk * 16], LDA);
#pragma unroll
        for (int j = 0; j < CFRAGS; j++) {
            wmma::fragment<wmma::matrix_b, 16, 16, 16, __half, wmma::row_major> bfrag;
            wmma::load_matrix_sync(bfrag, &Bsm[kk * 16][col0 + 16 * j], LDB);
            wmma::mma_sync(cfrag[j], afrag, bfrag, cfrag[j]);
        }
    }
    __syncthreads();
#pragma unroll
    for (int j = 0; j < CFRAGS; j++)
        wmma::store_matrix_sync(&Csm[rb][col0 + 16 * j], cfrag[j], LDC, wmma::mem_row_major);
    __syncthreads();

    for (int i = tid; i < 64 * NOUT / 2; i += 256) {
        int r = i / (NOUT / 2), c2 = i % (NOUT / 2);
        if (row0 + r < NN)
            *(__half2*)&g_h16[(row0 + r) * NOUT + c2 * 2] =
                __floats2half2_rn(Csm[r][c2 * 2], Csm[r][c2 * 2 + 1]);
    }
    constexpr int CPH = NOUT / HEADS;
    for (int idx = tid; idx < 64 * HEADS; idx += 256) {
        int r = idx / HEADS, h = idx % HEADS;
        float sd = 0.f, ss = 0.f;
#pragma unroll
        for (int c = 0; c < CPH; c++) {
            float v = Csm[r][h * CPH + c];
            sd += v * att[h * (2 * CPH) + c];
            ss += v * att[h * (2 * CPH) + CPH + c];
        }
        int row = row0 + r;
        if (row < NN) {
            g_adst[row * HEADS + h] = sd;
            g_asrc[row * HEADS + h] = ss;
        }
    }
}

__device__ __forceinline__ float leaky_exp(float a) {
    a = a > 0.f ? a : 0.2f * a;
    return __expf(a);
}

// ---------------- aggregate H=8: warp per node, 8-edge batches ----------------
__global__ __launch_bounds__(256) void k_agg8(const float* __restrict__ bias, int do_elu) {
    int t = blockIdx.x * blockDim.x + threadIdx.x;
    int n = t >> 5, lane = t & 31;
    if (n >= NN) return;
    const unsigned full = 0xffffffffu;
    int start = g_rowptr[n], end = g_rowptr[n + 1];
    int hA = lane & 7;
    int hB = lane >> 2;
    int eoff = lane >> 3;

    float adstA = g_adst[n * 8 + hA];
    float2 acc = make_float2(0.f, 0.f);
    float dsum = 0.f;

    for (int base = start; base < end; base += 8) {
        int eA = base + eoff;
        int eB = eA + 4;
        int validA = eA < end;
        int validB = eB < end;
        int ecA = validA ? eA : end - 1;
        int ecB = validB ? eB : end - 1;
        int sA = g_col[ecA];
        int sB = g_col[ecB];
        float aA = g_asrc[sA * 8 + hA];
        float aB = g_asrc[sB * 8 + hA];

        int s0 = __shfl_sync(full, sA, 0);
        int s1 = __shfl_sync(full, sA, 8);
        int s2 = __shfl_sync(full, sA, 16);
        int s3 = __shfl_sync(full, sA, 24);
        int s4 = __shfl_sync(full, sB, 0);
        int s5 = __shfl_sync(full, sB, 8);
        int s6 = __shfl_sync(full, sB, 16);
        int s7 = __shfl_sync(full, sB, 24);
        float2 v0 = __half22float2(*(const __half2*)&g_h16[s0 * 64 + lane * 2]);
        float2 v1 = __half22float2(*(const __half2*)&g_h16[s1 * 64 + lane * 2]);
        float2 v2 = __half22float2(*(const __half2*)&g_h16[s2 * 64 + lane * 2]);
        float2 v3 = __half22float2(*(const __half2*)&g_h16[s3 * 64 + lane * 2]);
        float2 v4 = __half22float2(*(const __half2*)&g_h16[s4 * 64 + lane * 2]);
        float2 v5 = __half22float2(*(const __half2*)&g_h16[s5 * 64 + lane * 2]);
        float2 v6 = __half22float2(*(const __half2*)&g_h16[s6 * 64 + lane * 2]);
        float2 v7 = __half22float2(*(const __half2*)&g_h16[s7 * 64 + lane * 2]);

        float exA = leaky_exp(adstA + aA);
        float exB = leaky_exp(adstA + aB);
        exA = validA ? exA : 0.f;
        exB = validB ? exB : 0.f;

        float w0 = __shfl_sync(full, exA, hB);
        float w1 = __shfl_sync(full, exA, 8 + hB);
        float w2 = __shfl_sync(full, exA, 16 + hB);
        float w3 = __shfl_sync(full, exA, 24 + hB);
        float w4 = __shfl_sync(full, exB, hB);
        float w5 = __shfl_sync(full, exB, 8 + hB);
        float w6 = __shfl_sync(full, exB, 16 + hB);
        float w7 = __shfl_sync(full, exB, 24 + hB);

        acc.x += v0.x * w0 + v1.x * w1 + v2.x * w2 + v3.x * w3;
        acc.x += v4.x * w4 + v5.x * w5 + v6.x * w6 + v7.x * w7;
        acc.y += v0.y * w0 + v1.y * w1 + v2.y * w2 + v3.y * w3;
        acc.y += v4.y * w4 + v5.y * w5 + v6.y * w6 + v7.y * w7;
        dsum += ((w0 + w1) + (w2 + w3)) + ((w4 + w5) + (w6 + w7));
    }
    float inv = 1.f / dsum;
    float o0 = acc.x * inv + bias[lane * 2];
    float o1 = acc.y * inv + bias[lane * 2 + 1];
    if (do_elu) {
        o0 = o0 > 0.f ? o0 : expm1f(o0);
        o1 = o1 > 0.f ? o1 : expm1f(o1);
    }
    *(__half2*)&g_act16[n * 64 + lane * 2] = __floats2half2_rn(o0, o1);
}

// ---------------- aggregate H=1: warp per node, 8-edge batches ----------------
// Phase A: lanes 0..7 -> edge slots (replicated x4), ONE warp-MUFU per 8 edges.
// Phase B: half-warp per edge (16 lanes x half2 = one 64B row), 2 edges per LDG,
// straight-line 4 gathers per iteration. Clamp+mask padding, no tail loop.
__global__ __launch_bounds__(256) void k_agg32(const float* __restrict__ bias,
                                               float* __restrict__ outp) {
    int t = blockIdx.x * blockDim.x + threadIdx.x;
    int n = t >> 5, lane = t & 31;
    if (n >= NN) return;
    const unsigned full = 0xffffffffu;
    int start = g_rowptr[n], end = g_rowptr[n + 1];
    int half = lane >> 4;       // 0: even slots, 1: odd slots
    int c2 = (lane & 15) * 2;   // 2 cols per lane
    int eoff = lane & 7;        // phase-A edge slot

    float adst = g_adst[n];
    float2 acc = make_float2(0.f, 0.f);
    float dsum = 0.f;

    for (int base = start; base < end; base += 8) {
        int e = base + eoff;
        int valid = e < end;
        int ec = valid ? e : end - 1;
        int scol = g_col[ec];
        float ex = leaky_exp(adst + g_asrc[scol]);
        ex = valid ? ex : 0.f;

        int i0 = half, i1 = 2 + half, i2 = 4 + half, i3 = 6 + half;
        int s0 = __shfl_sync(full, scol, i0);
        int s1 = __shfl_sync(full, scol, i1);
        int s2 = __shfl_sync(full, scol, i2);
        int s3 = __shfl_sync(full, scol, i3);
        float2 v0 = __half22float2(*(const __half2*)&g_h16[s0 * 32 + c2]);
        float2 v1 = __half22float2(*(const __half2*)&g_h16[s1 * 32 + c2]);
        float2 v2 = __half22float2(*(const __half2*)&g_h16[s2 * 32 + c2]);
        float2 v3 = __half22float2(*(const __half2*)&g_h16[s3 * 32 + c2]);
        float w0 = __shfl_sync(full, ex, i0);
        float w1 = __shfl_sync(full, ex, i1);
        float w2 = __shfl_sync(full, ex, i2);
        float w3 = __shfl_sync(full, ex, i3);

        acc.x += v0.x * w0 + v1.x * w1 + v2.x * w2 + v3.x * w3;
        acc.y += v0.y * w0 + v1.y * w1 + v2.y * w2 + v3.y * w3;
        dsum += (w0 + w1) + (w2 + w3);
    }
    // combine the two edge-slot halves
    acc.x += __shfl_xor_sync(full, acc.x, 16);
    acc.y += __shfl_xor_sync(full, acc.y, 16);
    dsum += __shfl_xor_sync(full, dsum, 16);
    if (lane < 16) {
        float inv = 1.f / dsum;
        outp[n * 32 + c2] = acc.x * inv + bias[c2];
        outp[n * 32 + c2 + 1] = acc.y * inv + bias[c2 + 1];
    }
}

// ---------------- launch ----------------
extern "C" void kernel_launch(void* const* d_in, const int* in_sizes, int n_in,
                              void* d_out, int out_size) {
    const float* x    = (const float*)d_in[0];
    const void*  ei   = d_in[1];
    const float* W1   = (const float*)d_in[2];
    const float* att1 = (const float*)d_in[3];
    const float* b1   = (const float*)d_in[4];
    const float* W2   = (const float*)d_in[5];
    const float* att2 = (const float*)d_in[6];
    const float* b2   = (const float*)d_in[7];
    const float* W3   = (const float*)d_in[8];
    const float* att3 = (const float*)d_in[9];
    const float* b3   = (const float*)d_in[10];
    float* out = (float*)d_out;

    const int TB = 256;
    const int warpGrid = (NN * 32 + TB - 1) / TB;
    const int gemmGrid = (NN + 63) / 64;

    // CSR build (dst layer-invariant); g_deg zeroed by previous call / load-time init
    k_convhist<<<(EE + TB - 1) / TB, TB>>>(ei);
    k_scan1<<<NB, 1024>>>();
    k_scan23<<<(NN + 255) / 256, 256>>>();
    k_scatter<<<(EE + NN + TB - 1) / TB, TB>>>();

    // Layer 1: 128 -> 8x8
    k_gemm_wmma<128, 64, 8, false><<<gemmGrid, TB>>>(x, W1, att1);
    k_agg8<<<warpGrid, TB>>>(b1, 1);

    // Layer 2: 64 -> 8x8
    k_gemm_wmma<64, 64, 8, true><<<gemmGrid, TB>>>(nullptr, W2, att2);
    k_agg8<<<warpGrid, TB>>>(b2, 1);

    // Layer 3: 64 -> 1x32
    k_gemm_wmma<64, 32, 1, true><<<gemmGrid, TB>>>(nullptr, W3, att3);
    k_agg32<<<warpGrid, TB>>>(b3, out);
}

// round 11
// speedup vs baseline: 1.9374x; 1.0007x over previous
#include <cuda_runtime.h>
#include <cuda_fp16.h>
#include <mma.h>

using namespace nvcuda;

#define NN 100000
#define EE 1600000
#define EQ 400000   // EE/4
#define NB 98       // (NN + 1023) / 1024

// ---------------- scratch (static device globals; no allocation) ----------------
__device__ int    g_deg[NN];      // zero-init at load; re-zeroed by k_scan23 each call
__device__ int    g_rowptr[NN + 1];
__device__ int    g_cursor[NN];
__device__ int    g_bsum[128];
__device__ int    g_col[EE + NN];
__device__ __half g_h16[NN * 64];
__device__ __half g_act16[NN * 64];
__device__ float  g_adst[NN * 8];
__device__ float  g_asrc[NN * 8];

// dtype sniff: int64 indices in range -> is64 (8 loads from one cached line)
__device__ __forceinline__ int sniff64(const long long* p64) {
    int is64 = 1;
#pragma unroll
    for (int k = 0; k < 8; k++) {
        long long v = p64[k];
        if (v < 0 || v >= NN) is64 = 0;
    }
    return is64;
}

// ---------------- histogram: 4 edges/thread, independent atomics ----------------
__global__ void k_hist(const void* ei) {
    int t = blockIdx.x * blockDim.x + threadIdx.x;
    if (t >= EQ) return;
    const long long* p64 = (const long long*)ei;
    int is64 = sniff64(p64);
    int e0 = t * 4;
    int s[4], d[4];
    if (is64) {
#pragma unroll
        for (int j = 0; j < 4; j++) {
            s[j] = (int)p64[e0 + j];
            d[j] = (int)p64[EE + e0 + j];
        }
    } else {
        const int* p = (const int*)ei;
#pragma unroll
        for (int j = 0; j < 4; j++) {
            s[j] = p[e0 + j];
            d[j] = p[EE + e0 + j];
        }
    }
#pragma unroll
    for (int j = 0; j < 4; j++)
        if (s[j] != d[j]) atomicAdd(&g_deg[d[j]], 1);  // self-loops dropped (exp(-1e9-amax)==0)
}

// ---------------- scan (self-loop +1 folded in) ----------------
__global__ void k_scan1() {
    __shared__ int sh[1024];
    int tid = threadIdx.x;
    int i = blockIdx.x * 1024 + tid;
    int v = (i < NN) ? g_deg[i] + 1 : 0;  // +1 = appended self-loop
    sh[tid] = v;
    __syncthreads();
    for (int o = 1; o < 1024; o <<= 1) {
        int t = (tid >= o) ? sh[tid - o] : 0;
        __syncthreads();
        sh[tid] += t;
        __syncthreads();
    }
    if (i < NN) g_rowptr[i] = sh[tid] - v;
    if (tid == 1023) g_bsum[blockIdx.x] = sh[1023];
}

__global__ void k_scan23() {
    __shared__ int sh[128];
    int tid = threadIdx.x;
    int i = blockIdx.x * 256 + tid;
    if (tid < 128) sh[tid] = (tid < NB) ? g_bsum[tid] : 0;
    __syncthreads();
    for (int o = 1; o < 128; o <<= 1) {
        int t = (tid >= o && tid < 128) ? sh[tid - o] : 0;
        __syncthreads();
        if (tid < 128) sh[tid] += t;
        __syncthreads();
    }
    if (i < NN) {
        int blk = i >> 10;
        int exc = blk ? sh[blk - 1] : 0;
        int r = g_rowptr[i] + exc;
        g_rowptr[i] = r;
        g_cursor[i] = r;
        g_deg[i] = 0;  // reset for next call (deg fully consumed by scan1)
    }
    if (blockIdx.x == 0 && tid == 0) g_rowptr[NN] = sh[127];
}

// ---------------- scatter: 4 edges/thread, reads edge_index directly ----------------
__global__ void k_scatter(const void* ei) {
    int t = blockIdx.x * blockDim.x + threadIdx.x;
    if (t < EQ) {
        const long long* p64 = (const long long*)ei;
        int is64 = sniff64(p64);
        int e0 = t * 4;
        int s[4], d[4];
        if (is64) {
#pragma unroll
            for (int j = 0; j < 4; j++) {
                s[j] = (int)p64[e0 + j];
                d[j] = (int)p64[EE + e0 + j];
            }
        } else {
            const int* p = (const int*)ei;
#pragma unroll
            for (int j = 0; j < 4; j++) {
                s[j] = p[e0 + j];
                d[j] = p[EE + e0 + j];
            }
        }
        int pos[4];
#pragma unroll
        for (int j = 0; j < 4; j++)
            pos[j] = (s[j] != d[j]) ? atomicAdd(&g_cursor[d[j]], 1) : -1;
#pragma unroll
        for (int j = 0; j < 4; j++)
            if (pos[j] >= 0) g_col[pos[j]] = s[j];
    } else {
        int n = t - EQ;
        if (n < NN) {
            int p = atomicAdd(&g_cursor[n], 1);
            g_col[p] = n;  // appended self-loop
        }
    }
}

// ---------------- wmma tensor-core GEMM + fused attention-dot epilogue ----------------
template <int K, int NOUT, int HEADS, bool HALF_A>
__global__ __launch_bounds__(256) void k_gemm_wmma(const float* __restrict__ Af,
                                                   const float* __restrict__ W,
                                                   const float* __restrict__ att) {
    constexpr int LDA = K + 8;
    constexpr int LDB = NOUT + 8;
    constexpr int LDC = NOUT + 8;
    constexpr int AB_BYTES = 64 * LDA * 2 + K * LDB * 2;
    constexpr int C_BYTES = 64 * LDC * 4;
    constexpr int SM_BYTES = AB_BYTES > C_BYTES ? AB_BYTES : C_BYTES;
    __shared__ __align__(16) char smem[SM_BYTES];
    __half (*Asm)[LDA] = reinterpret_cast<__half (*)[LDA]>(smem);
    __half (*Bsm)[LDB] = reinterpret_cast<__half (*)[LDB]>(smem + 64 * LDA * 2);
    float  (*Csm)[LDC] = reinterpret_cast<float (*)[LDC]>(smem);

    int tid = threadIdx.x;
    int w = tid >> 5;
    int row0 = blockIdx.x * 64;

    for (int i = tid; i < K * NOUT / 4; i += 256) {
        int r = i / (NOUT / 4), c4 = i % (NOUT / 4);
        float4 v = ((const float4*)W)[i];
        __half2* dst = (__half2*)&Bsm[r][c4 * 4];
        dst[0] = __floats2half2_rn(v.x, v.y);
        dst[1] = __floats2half2_rn(v.z, v.w);
    }
    if (HALF_A) {
        for (int i = tid; i < 64 * K / 8; i += 256) {
            int r = i / (K / 8), c8 = i % (K / 8);
            float4 v = make_float4(0.f, 0.f, 0.f, 0.f);
            if (row0 + r < NN)
                v = *(const float4*)&g_act16[(row0 + r) * K + c8 * 8];
            *(float4*)&Asm[r][c8 * 8] = v;
        }
    } else {
        for (int i = tid; i < 64 * K / 4; i += 256) {
            int r = i / (K / 4), c4 = i % (K / 4);
            float4 v = make_float4(0.f, 0.f, 0.f, 0.f);
            if (row0 + r < NN)
                v = *(const float4*)&Af[(row0 + r) * K + c4 * 4];
            __half2* dst = (__half2*)&Asm[r][c4 * 4];
            dst[0] = __floats2half2_rn(v.x, v.y);
            dst[1] = __floats2half2_rn(v.z, v.w);
        }
    }
    __syncthreads();

    constexpr int CFRAGS = NOUT / 32;
    int rb = (w >> 1) * 16;
    int col0 = (w & 1) * (NOUT / 2);

    wmma::fragment<wmma::accumulator, 16, 16, 16, float> cfrag[CFRAGS];
#pragma unroll
    for (int j = 0; j < CFRAGS; j++) wmma::fill_fragment(cfrag[j], 0.f);

#pragma unroll
    for (int kk = 0; kk < K / 16; kk++) {
        wmma::fragment<wmma::matrix_a, 16, 16, 16, __half, wmma::row_major> afrag;
        wmma::load_matrix_sync(afrag, &Asm[rb][kk * 16], LDA);
#pragma unroll
        for (int j = 0; j < CFRAGS; j++) {
            wmma::fragment<wmma::matrix_b, 16, 16, 16, __half, wmma::row_major> bfrag;
            wmma::load_matrix_sync(bfrag, &Bsm[kk * 16][col0 + 16 * j], LDB);
            wmma::mma_sync(cfrag[j], afrag, bfrag, cfrag[j]);
        }
    }
    __syncthreads();
#pragma unroll
    for (int j = 0; j < CFRAGS; j++)
        wmma::store_matrix_sync(&Csm[rb][col0 + 16 * j], cfrag[j], LDC, wmma::mem_row_major);
    __syncthreads();

    for (int i = tid; i < 64 * NOUT / 2; i += 256) {
        int r = i / (NOUT / 2), c2 = i % (NOUT / 2);
        if (row0 + r < NN)
            *(__half2*)&g_h16[(row0 + r) * NOUT + c2 * 2] =
                __floats2half2_rn(Csm[r][c2 * 2], Csm[r][c2 * 2 + 1]);
    }
    constexpr int CPH = NOUT / HEADS;
    for (int idx = tid; idx < 64 * HEADS; idx += 256) {
        int r = idx / HEADS, h = idx % HEADS;
        float sd = 0.f, ss = 0.f;
#pragma unroll
        for (int c = 0; c < CPH; c++) {
            float v = Csm[r][h * CPH + c];
            sd += v * att[h * (2 * CPH) + c];
            ss += v * att[h * (2 * CPH) + CPH + c];
        }
        int row = row0 + r;
        if (row < NN) {
            g_adst[row * HEADS + h] = sd;
            g_asrc[row * HEADS + h] = ss;
        }
    }
}

__device__ __forceinline__ float leaky_exp(float a) {
    a = a > 0.f ? a : 0.2f * a;
    return __expf(a);
}

// ---------------- aggregate H=8: warp per node, 8-edge batches ----------------
__global__ __launch_bounds__(256) void k_agg8(const float* __restrict__ bias, int do_elu) {
    int t = blockIdx.x * blockDim.x + threadIdx.x;
    int n = t >> 5, lane = t & 31;
    if (n >= NN) return;
    const unsigned full = 0xffffffffu;
    int start = g_rowptr[n], end = g_rowptr[n + 1];
    int hA = lane & 7;
    int hB = lane >> 2;
    int eoff = lane >> 3;

    float adstA = g_adst[n * 8 + hA];
    float2 acc = make_float2(0.f, 0.f);
    float dsum = 0.f;

    for (int base = start; base < end; base += 8) {
        int eA = base + eoff;
        int eB = eA + 4;
        int validA = eA < end;
        int validB = eB < end;
        int ecA = validA ? eA : end - 1;
        int ecB = validB ? eB : end - 1;
        int sA = g_col[ecA];
        int sB = g_col[ecB];
        float aA = g_asrc[sA * 8 + hA];
        float aB = g_asrc[sB * 8 + hA];

        int s0 = __shfl_sync(full, sA, 0);
        int s1 = __shfl_sync(full, sA, 8);
        int s2 = __shfl_sync(full, sA, 16);
        int s3 = __shfl_sync(full, sA, 24);
        int s4 = __shfl_sync(full, sB, 0);
        int s5 = __shfl_sync(full, sB, 8);
        int s6 = __shfl_sync(full, sB, 16);
        int s7 = __shfl_sync(full, sB, 24);
        float2 v0 = __half22float2(*(const __half2*)&g_h16[s0 * 64 + lane * 2]);
        float2 v1 = __half22float2(*(const __half2*)&g_h16[s1 * 64 + lane * 2]);
        float2 v2 = __half22float2(*(const __half2*)&g_h16[s2 * 64 + lane * 2]);
        float2 v3 = __half22float2(*(const __half2*)&g_h16[s3 * 64 + lane * 2]);
        float2 v4 = __half22float2(*(const __half2*)&g_h16[s4 * 64 + lane * 2]);
        float2 v5 = __half22float2(*(const __half2*)&g_h16[s5 * 64 + lane * 2]);
        float2 v6 = __half22float2(*(const __half2*)&g_h16[s6 * 64 + lane * 2]);
        float2 v7 = __half22float2(*(const __half2*)&g_h16[s7 * 64 + lane * 2]);

        float exA = leaky_exp(adstA + aA);
        float exB = leaky_exp(adstA + aB);
        exA = validA ? exA : 0.f;
        exB = validB ? exB : 0.f;

        float w0 = __shfl_sync(full, exA, hB);
        float w1 = __shfl_sync(full, exA, 8 + hB);
        float w2 = __shfl_sync(full, exA, 16 + hB);
        float w3 = __shfl_sync(full, exA, 24 + hB);
        float w4 = __shfl_sync(full, exB, hB);
        float w5 = __shfl_sync(full, exB, 8 + hB);
        float w6 = __shfl_sync(full, exB, 16 + hB);
        float w7 = __shfl_sync(full, exB, 24 + hB);

        acc.x += v0.x * w0 + v1.x * w1 + v2.x * w2 + v3.x * w3;
        acc.x += v4.x * w4 + v5.x * w5 + v6.x * w6 + v7.x * w7;
        acc.y += v0.y * w0 + v1.y * w1 + v2.y * w2 + v3.y * w3;
        acc.y += v4.y * w4 + v5.y * w5 + v6.y * w6 + v7.y * w7;
        dsum += ((w0 + w1) + (w2 + w3)) + ((w4 + w5) + (w6 + w7));
    }
    float inv = 1.f / dsum;
    float o0 = acc.x * inv + bias[lane * 2];
    float o1 = acc.y * inv + bias[lane * 2 + 1];
    if (do_elu) {
        o0 = o0 > 0.f ? o0 : expm1f(o0);
        o1 = o1 > 0.f ? o1 : expm1f(o1);
    }
    *(__half2*)&g_act16[n * 64 + lane * 2] = __floats2half2_rn(o0, o1);
}

// ---------------- aggregate H=1: warp per node, 8-edge batches ----------------
__global__ __launch_bounds__(256) void k_agg32(const float* __restrict__ bias,
                                               float* __restrict__ outp) {
    int t = blockIdx.x * blockDim.x + threadIdx.x;
    int n = t >> 5, lane = t & 31;
    if (n >= NN) return;
    const unsigned full = 0xffffffffu;
    int start = g_rowptr[n], end = g_rowptr[n + 1];
    int half = lane >> 4;
    int c2 = (lane & 15) * 2;
    int eoff = lane & 7;

    float adst = g_adst[n];
    float2 acc = make_float2(0.f, 0.f);
    float dsum = 0.f;

    for (int base = start; base < end; base += 8) {
        int e = base + eoff;
        int valid = e < end;
        int ec = valid ? e : end - 1;
        int scol = g_col[ec];
        float ex = leaky_exp(adst + g_asrc[scol]);
        ex = valid ? ex : 0.f;

        int i0 = half, i1 = 2 + half, i2 = 4 + half, i3 = 6 + half;
        int s0 = __shfl_sync(full, scol, i0);
        int s1 = __shfl_sync(full, scol, i1);
        int s2 = __shfl_sync(full, scol, i2);
        int s3 = __shfl_sync(full, scol, i3);
        float2 v0 = __half22float2(*(const __half2*)&g_h16[s0 * 32 + c2]);
        float2 v1 = __half22float2(*(const __half2*)&g_h16[s1 * 32 + c2]);
        float2 v2 = __half22float2(*(const __half2*)&g_h16[s2 * 32 + c2]);
        float2 v3 = __half22float2(*(const __half2*)&g_h16[s3 * 32 + c2]);
        float w0 = __shfl_sync(full, ex, i0);
        float w1 = __shfl_sync(full, ex, i1);
        float w2 = __shfl_sync(full, ex, i2);
        float w3 = __shfl_sync(full, ex, i3);

        acc.x += v0.x * w0 + v1.x * w1 + v2.x * w2 + v3.x * w3;
        acc.y += v0.y * w0 + v1.y * w1 + v2.y * w2 + v3.y * w3;
        dsum += (w0 + w1) + (w2 + w3);
    }
    acc.x += __shfl_xor_sync(full, acc.x, 16);
    acc.y += __shfl_xor_sync(full, acc.y, 16);
    dsum += __shfl_xor_sync(full, dsum, 16);
    if (lane < 16) {
        float inv = 1.f / dsum;
        outp[n * 32 + c2] = acc.x * inv + bias[c2];
        outp[n * 32 + c2 + 1] = acc.y * inv + bias[c2 + 1];
    }
}

// ---------------- launch ----------------
extern "C" void kernel_launch(void* const* d_in, const int* in_sizes, int n_in,
                              void* d_out, int out_size) {
    const float* x    = (const float*)d_in[0];
    const void*  ei   = d_in[1];
    const float* W1   = (const float*)d_in[2];
    const float* att1 = (const float*)d_in[3];
    const float* b1   = (const float*)d_in[4];
    const float* W2   = (const float*)d_in[5];
    const float* att2 = (const float*)d_in[6];
    const float* b2   = (const float*)d_in[7];
    const float* W3   = (const float*)d_in[8];
    const float* att3 = (const float*)d_in[9];
    const float* b3   = (const float*)d_in[10];
    float* out = (float*)d_out;

    const int TB = 256;
    const int warpGrid = (NN * 32 + TB - 1) / TB;
    const int gemmGrid = (NN + 63) / 64;

    // CSR build (dst layer-invariant); g_deg zeroed by previous call / load-time init
    k_hist<<<(EQ + TB - 1) / TB, TB>>>(ei);
    k_scan1<<<NB, 1024>>>();
    k_scan23<<<(NN + 255) / 256, 256>>>();
    k_scatter<<<(EQ + NN + TB - 1) / TB, TB>>>(ei);

    // Layer 1: 128 -> 8x8
    k_gemm_wmma<128, 64, 8, false><<<gemmGrid, TB>>>(x, W1, att1);
    k_agg8<<<warpGrid, TB>>>(b1, 1);

    // Layer 2: 64 -> 8x8
    k_gemm_wmma<64, 64, 8, true><<<gemmGrid, TB>>>(nullptr, W2, att2);
    k_agg8<<<warpGrid, TB>>>(b2, 1);

    // Layer 3: 64 -> 1x32
    k_gemm_wmma<64, 32, 1, true><<<gemmGrid, TB>>>(nullptr, W3, att3);
    k_agg32<<<warpGrid, TB>>>(b3, out);
}